// round 15
// baseline (speedup 1.0000x reference)
#include <cuda_runtime.h>
#include <cuda_bf16.h>
#include <math.h>
#include <math_constants.h>
#include <stdint.h>

#define NN   50000
#define EE   300000
#define DIN  1024
#define HID  512
#define DOUT 30

#define W2S_BYTES (HID * 31 * 4)     // 63488 B, stride-31 rows (bank-conflict-free)

// ---------------- scratch (no allocs allowed) ----------------
__device__ float g_h[(size_t)NN * HID];      // h = X @ W1
__device__ float g_h3[(size_t)NN * HID];     // h3 = elu(a30 @ W2^T)
__device__ float g_a30[(size_t)NN * DOUT];   // 30-dim aggregation of h2
__device__ int   g_cnt[NN];                  // zeroed at start (static init + scan re-zeroes)
__device__ int   g_rowptr[NN + 1];
__device__ int   g_cur[NN];
__device__ int   g_csrc[EE];
__device__ float g_w[EE];

// ---------------- CSR build ----------------
__global__ void k_hist(const int* __restrict__ dst, int E) {
    int e = blockIdx.x * 256 + threadIdx.x;
    if (e < E) atomicAdd(&g_cnt[dst[e]], 1);
}
__global__ __launch_bounds__(1024) void k_scan(int n, int E) {
    __shared__ int sums[1024];
    int t = threadIdx.x;
    int chunk = (n + 1023) >> 10;
    int s0 = t * chunk, s1 = min(s0 + chunk, n);
    int local = 0;
    for (int i = s0; i < s1; i++) local += g_cnt[i];
    sums[t] = local;
    __syncthreads();
    #pragma unroll
    for (int off = 1; off < 1024; off <<= 1) {
        int x = (t >= off) ? sums[t - off] : 0;
        __syncthreads();
        sums[t] += x;
        __syncthreads();
    }
    int run = sums[t] - local;
    for (int i = s0; i < s1; i++) {
        int c = g_cnt[i];
        g_cnt[i] = 0;            // re-zero for the NEXT graph replay
        g_rowptr[i] = run;
        g_cur[i] = run;
        run += c;
    }
    if (t == 0) g_rowptr[n] = E;
}
__global__ void k_scatter(const int* __restrict__ src, const int* __restrict__ dst, int E) {
    int e = blockIdx.x * 256 + threadIdx.x;
    if (e >= E) return;
    int pos = atomicAdd(&g_cur[dst[e]], 1);
    g_csrc[pos] = src[e];
}

// ================= tensor-core GEMM: C[M,N] = A[M,K] @ B[K,N] =================
// fp32 in/out, internally bf16 hi/lo split (3 mma products) for ~1e-5 accuracy.
// Register-lean fragment schedule (A-frags loaded per-mf) so 2 CTAs fit per SM:
// one CTA's mma phase hides the other's load/split/sync phase.

__device__ __forceinline__ void ldm_x4(uint32_t* r, uint32_t addr) {
    asm volatile("ldmatrix.sync.aligned.m8n8.x4.shared.b16 {%0,%1,%2,%3}, [%4];"
        : "=r"(r[0]), "=r"(r[1]), "=r"(r[2]), "=r"(r[3]) : "r"(addr));
}
__device__ __forceinline__ void ldm_x2t(uint32_t* r, uint32_t addr) {
    asm volatile("ldmatrix.sync.aligned.m8n8.x2.trans.shared.b16 {%0,%1}, [%2];"
        : "=r"(r[0]), "=r"(r[1]) : "r"(addr));
}
__device__ __forceinline__ void mma16816(float* c, const uint32_t* a, const uint32_t* b) {
    asm volatile("mma.sync.aligned.m16n8k16.row.col.f32.bf16.bf16.f32 "
        "{%0,%1,%2,%3}, {%4,%5,%6,%7}, {%8,%9}, {%0,%1,%2,%3};"
        : "+f"(c[0]), "+f"(c[1]), "+f"(c[2]), "+f"(c[3])
        : "r"(a[0]), "r"(a[1]), "r"(a[2]), "r"(a[3]), "r"(b[0]), "r"(b[1]));
}
__device__ __forceinline__ void split2(float x, __nv_bfloat16& h, __nv_bfloat16& l) {
    h = __float2bfloat16(x);
    l = __float2bfloat16(x - __bfloat162float(h));
}

#define APAD 8
#define BPAD 8

__global__ __launch_bounds__(256, 2) void k_mma_split(
    const float* __restrict__ A, const float* __restrict__ B,
    float* __restrict__ C, int M, int N, int K)
{
    __shared__ __nv_bfloat16 As[2][128][32 + APAD];
    __shared__ __nv_bfloat16 Bs[2][32][128 + BPAD];

    const int tid  = threadIdx.x;
    const int lane = tid & 31;
    const int wid  = tid >> 5;
    const int wm   = (wid & 1) * 64;
    const int wn   = (wid >> 1) * 32;
    const int bm   = blockIdx.y * 128;
    const int bn   = blockIdx.x * 128;

    float acc[4][4][4] = {};

    for (int k0 = 0; k0 < K; k0 += 32) {
        #pragma unroll
        for (int i = 0; i < 4; i++) {
            int idx = tid + i * 256;
            int r  = idx >> 3;
            int c4 = (idx & 7) * 4;
            float4 v = make_float4(0.f, 0.f, 0.f, 0.f);
            if (bm + r < M) v = *(const float4*)(A + (size_t)(bm + r) * K + k0 + c4);
            union { __nv_bfloat16 b[4]; uint2 u; } ph, pl;
            split2(v.x, ph.b[0], pl.b[0]); split2(v.y, ph.b[1], pl.b[1]);
            split2(v.z, ph.b[2], pl.b[2]); split2(v.w, ph.b[3], pl.b[3]);
            *(uint2*)&As[0][r][c4] = ph.u;
            *(uint2*)&As[1][r][c4] = pl.u;
        }
        #pragma unroll
        for (int i = 0; i < 4; i++) {
            int idx = tid + i * 256;
            int r  = idx >> 5;
            int c4 = (idx & 31) * 4;
            float4 v = *(const float4*)(B + (size_t)(k0 + r) * N + bn + c4);
            union { __nv_bfloat16 b[4]; uint2 u; } ph, pl;
            split2(v.x, ph.b[0], pl.b[0]); split2(v.y, ph.b[1], pl.b[1]);
            split2(v.z, ph.b[2], pl.b[2]); split2(v.w, ph.b[3], pl.b[3]);
            *(uint2*)&Bs[0][r][c4] = ph.u;
            *(uint2*)&Bs[1][r][c4] = pl.u;
        }
        __syncthreads();

        #pragma unroll
        for (int ks = 0; ks < 2; ks++) {
            // B fragments: loaded once per ks, shared across all mf
            uint32_t bh[4][2], bl[4][2];
            #pragma unroll
            for (int nf = 0; nf < 4; nf++) {
                int rr = ks * 16 + (lane & 15);
                int cc = wn + nf * 8;
                ldm_x2t(bh[nf], (uint32_t)__cvta_generic_to_shared(&Bs[0][rr][cc]));
                ldm_x2t(bl[nf], (uint32_t)__cvta_generic_to_shared(&Bs[1][rr][cc]));
            }
            // A fragments: loaded per-mf to keep register pressure low (2 CTAs/SM)
            #pragma unroll
            for (int mf = 0; mf < 4; mf++) {
                uint32_t ah[4], al[4];
                int rr = wm + mf * 16 + (lane & 15);
                int cc = ks * 16 + (lane >> 4) * 8;
                ldm_x4(ah, (uint32_t)__cvta_generic_to_shared(&As[0][rr][cc]));
                ldm_x4(al, (uint32_t)__cvta_generic_to_shared(&As[1][rr][cc]));
                #pragma unroll
                for (int nf = 0; nf < 4; nf++) {
                    mma16816(acc[mf][nf], ah, bh[nf]);
                    mma16816(acc[mf][nf], ah, bl[nf]);
                    mma16816(acc[mf][nf], al, bh[nf]);
                }
            }
        }
        __syncthreads();
    }

    #pragma unroll
    for (int mf = 0; mf < 4; mf++) {
        int r0 = bm + wm + mf * 16 + (lane >> 2);
        #pragma unroll
        for (int nf = 0; nf < 4; nf++) {
            int c = bn + wn + nf * 8 + (lane & 3) * 2;
            if (r0 < M) {
                C[(size_t)r0 * N + c]     = acc[mf][nf][0];
                C[(size_t)r0 * N + c + 1] = acc[mf][nf][1];
            }
            if (r0 + 8 < M) {
                C[(size_t)(r0 + 8) * N + c]     = acc[mf][nf][2];
                C[(size_t)(r0 + 8) * N + c + 1] = acc[mf][nf][3];
            }
        }
    }
}

// ======= fused per-node: scores + online softmax + agg + ELU + (@W2) =======
// W2 staged in swizzled shared memory (stride 31, conflict-free epilogue LDS).
__global__ __launch_bounds__(256) void k_attn(const float* __restrict__ att,
                                              const float* __restrict__ W2,
                                              float* __restrict__ h2, int n)
{
    extern __shared__ float W2s[];   // [512 rows][stride 31]
    int tid = threadIdx.y * 32 + threadIdx.x;
    for (int idx = tid; idx < HID * DOUT; idx += 256) {
        int k = idx / DOUT, j = idx % DOUT;
        int row = (k & 3) * 128 + (k >> 2);
        W2s[row * 31 + j] = W2[idx];
    }
    __syncthreads();

    int d = blockIdx.x * 8 + threadIdx.y;
    int lane = threadIdx.x;
    if (d < n) {
        int beg = g_rowptr[d], end = g_rowptr[d + 1];

        const float4* hdp = (const float4*)(g_h + (size_t)d * HID);
        const float4* ap  = (const float4*)att;
        float4 hd[4], av[4];
        #pragma unroll
        for (int i = 0; i < 4; i++) {
            hd[i] = hdp[i * 32 + lane];
            av[i] = __ldg(&ap[i * 32 + lane]);
        }

        float m = -CUDART_INF_F, den = 0.f;
        float4 acc[4];
        #pragma unroll
        for (int i = 0; i < 4; i++) acc[i] = make_float4(0.f, 0.f, 0.f, 0.f);

        float4 nb[4];
        if (beg < end) {
            const float4* p0 = (const float4*)(g_h + (size_t)g_csrc[beg] * HID);
            #pragma unroll
            for (int i = 0; i < 4; i++) nb[i] = p0[i * 32 + lane];
        }

        for (int j = beg; j < end; j++) {
            float4 hs[4];
            #pragma unroll
            for (int i = 0; i < 4; i++) hs[i] = nb[i];

            if (j + 1 < end) {
                const float4* pn = (const float4*)(g_h + (size_t)g_csrc[j + 1] * HID);
                #pragma unroll
                for (int i = 0; i < 4; i++) nb[i] = pn[i * 32 + lane];
            }

            float p = 0.f;
            #pragma unroll
            for (int i = 0; i < 4; i++) {
                float4 a = hd[i];
                float4 b = hs[i];
                float v;
                v = a.x + b.x; v = v > 0.f ? v : 0.2f * v; p = fmaf(v, av[i].x, p);
                v = a.y + b.y; v = v > 0.f ? v : 0.2f * v; p = fmaf(v, av[i].y, p);
                v = a.z + b.z; v = v > 0.f ? v : 0.2f * v; p = fmaf(v, av[i].z, p);
                v = a.w + b.w; v = v > 0.f ? v : 0.2f * v; p = fmaf(v, av[i].w, p);
            }
            #pragma unroll
            for (int o = 16; o; o >>= 1) p += __shfl_xor_sync(0xffffffffu, p, o);

            if (lane == 0) g_w[j] = p;

            if (p > m) {
                float scale = expf(m - p);
                den *= scale;
                #pragma unroll
                for (int i = 0; i < 4; i++) {
                    acc[i].x *= scale; acc[i].y *= scale;
                    acc[i].z *= scale; acc[i].w *= scale;
                }
                m = p;
            }
            float w = expf(p - m);
            den += w;
            #pragma unroll
            for (int i = 0; i < 4; i++) {
                acc[i].x = fmaf(w, hs[i].x, acc[i].x);
                acc[i].y = fmaf(w, hs[i].y, acc[i].y);
                acc[i].z = fmaf(w, hs[i].z, acc[i].z);
                acc[i].w = fmaf(w, hs[i].w, acc[i].w);
            }
        }

        float h2acc[DOUT];
        #pragma unroll
        for (int j = 0; j < DOUT; j++) h2acc[j] = 0.f;

        if (end > beg) {
            float inv = 1.f / den;
            #pragma unroll
            for (int i = 0; i < 4; i++) {
                float hv[4];
                hv[0] = acc[i].x * inv; hv[0] = hv[0] > 0.f ? hv[0] : expm1f(hv[0]);
                hv[1] = acc[i].y * inv; hv[1] = hv[1] > 0.f ? hv[1] : expm1f(hv[1]);
                hv[2] = acc[i].z * inv; hv[2] = hv[2] > 0.f ? hv[2] : expm1f(hv[2]);
                hv[3] = acc[i].w * inv; hv[3] = hv[3] > 0.f ? hv[3] : expm1f(hv[3]);
                #pragma unroll
                for (int c = 0; c < 4; c++) {
                    const float* w2r = W2s + (size_t)(c * 128 + i * 32 + lane) * 31;
                    float x = hv[c];
                    #pragma unroll
                    for (int j = 0; j < DOUT; j++)
                        h2acc[j] = fmaf(x, w2r[j], h2acc[j]);
                }
            }
            for (int j = beg + lane; j < end; j += 32)
                g_w[j] = expf(g_w[j] - m) * inv;
        }

        #pragma unroll
        for (int j = 0; j < DOUT; j++)
            #pragma unroll
            for (int o = 16; o; o >>= 1)
                h2acc[j] += __shfl_xor_sync(0xffffffffu, h2acc[j], o);
        #pragma unroll
        for (int j = 0; j < DOUT; j++)
            if (lane == j) h2[(size_t)d * DOUT + j] = h2acc[j];
    }
}

// ======= 30-dim aggregation: a30[d] = sum_e w_e * h2[src_e] =======
__global__ __launch_bounds__(256) void k_agg30(const float* __restrict__ h2, int n)
{
    int d = blockIdx.x * 8 + threadIdx.y;
    if (d >= n) return;
    int lane = threadIdx.x;
    int beg = g_rowptr[d], end = g_rowptr[d + 1];

    float a = 0.f;
    float nv = 0.f, nw = 0.f;
    if (beg < end) {
        nw = g_w[beg];
        if (lane < DOUT) nv = h2[(size_t)g_csrc[beg] * DOUT + lane];
    }
    for (int j = beg; j < end; j++) {
        float v = nv, w = nw;
        if (j + 1 < end) {
            nw = g_w[j + 1];
            if (lane < DOUT) nv = h2[(size_t)g_csrc[j + 1] * DOUT + lane];
        }
        a = fmaf(w, v, a);
    }
    if (lane < DOUT) g_a30[(size_t)d * DOUT + lane] = a;
}

// ======= expand: h3 = elu(a30 @ W2^T), warp-per-node, W2 in smem =======
__global__ __launch_bounds__(256) void k_expand(const float* __restrict__ W2, int n)
{
    extern __shared__ float W2s[];   // [512][31]
    int tid = threadIdx.y * 32 + threadIdx.x;
    for (int idx = tid; idx < HID * DOUT; idx += 256) {
        int r = idx / DOUT, j = idx % DOUT;
        W2s[r * 31 + j] = W2[idx];
    }
    __syncthreads();

    int d = blockIdx.x * 8 + threadIdx.y;
    if (d >= n) return;
    int lane = threadIdx.x;

    float a[DOUT];
    const float* ar = g_a30 + (size_t)d * DOUT;
    #pragma unroll
    for (int j = 0; j < DOUT; j++) a[j] = __ldg(&ar[j]);

    float* op = g_h3 + (size_t)d * HID;
    #pragma unroll
    for (int mblk = 0; mblk < HID / 32; mblk++) {
        int c = mblk * 32 + lane;
        const float* w2r = W2s + (size_t)c * 31;
        float s = 0.f;
        #pragma unroll
        for (int j = 0; j < DOUT; j++) s = fmaf(a[j], w2r[j], s);
        op[c] = s > 0.f ? s : expm1f(s);
    }
}

// ---------------- launch ----------------
extern "C" void kernel_launch(void* const* d_in, const int* in_sizes, int n_in,
                              void* d_out, int out_size)
{
    const float* features = (const float*)d_in[0];
    const int*   eidx     = (const int*)d_in[1];
    const float* W1       = (const float*)d_in[2];
    const float* att1     = (const float*)d_in[3];
    const float* W2       = (const float*)d_in[4];
    const float* W4       = (const float*)d_in[5];
    float* out = (float*)d_out;

    const int n = in_sizes[0] / DIN;      // 50000
    const int E = in_sizes[1] / 2;        // 300000
    const int* src = eidx;
    const int* dst = eidx + E;

    float* h;   cudaGetSymbolAddress((void**)&h,   g_h);
    float* h3;  cudaGetSymbolAddress((void**)&h3,  g_h3);

    cudaFuncSetAttribute(k_attn,   cudaFuncAttributeMaxDynamicSharedMemorySize, W2S_BYTES);
    cudaFuncSetAttribute(k_expand, cudaFuncAttributeMaxDynamicSharedMemorySize, W2S_BYTES);

    const dim3 warp8(32, 8);

    // launches 0-2: CSR build
    k_hist<<<(E + 255) / 256, 256>>>(dst, E);
    k_scan<<<1, 1024>>>(n, E);
    k_scatter<<<(E + 255) / 256, 256>>>(src, dst, E);

    // launch 3 (ncu profiles THIS): h = X @ W1  (2 CTAs/SM register-lean)
    {
        dim3 g(HID / 128, (n + 127) / 128);
        k_mma_split<<<g, 256>>>(features, W1, h, n, HID, DIN);
    }

    // fused GATv2 + h2 projection (smem W2)
    k_attn<<<(n + 7) / 8, warp8, W2S_BYTES>>>(att1, W2, out, n);

    // 30-dim tied-alpha aggregation of h2
    k_agg30<<<(n + 7) / 8, warp8>>>(out, n);

    // h3 = elu(a30 @ W2^T)
    k_expand<<<(n + 7) / 8, warp8, W2S_BYTES>>>(W2, n);

    // h4 = h3 @ W4
    {
        dim3 g(DIN / 128, (n + 127) / 128);
        k_mma_split<<<g, 256>>>(h3, W4, out + (size_t)n * DOUT, n, DIN, HID);
    }
}

// round 16
// speedup vs baseline: 1.3437x; 1.3437x over previous
#include <cuda_runtime.h>
#include <cuda_bf16.h>
#include <math.h>
#include <math_constants.h>
#include <stdint.h>

#define NN   50000
#define EE   300000
#define DIN  1024
#define HID  512
#define DOUT 30

#define W2S_BYTES (HID * 31 * 4)     // 63488 B, stride-31 rows (bank-conflict-free)

// ---------------- scratch (no allocs allowed) ----------------
__device__ float g_h[(size_t)NN * HID];      // h = X @ W1
__device__ float g_h3[(size_t)NN * HID];     // h3 = elu(a30 @ W2^T)
__device__ float g_a30[(size_t)NN * DOUT];   // 30-dim aggregation of h2
__device__ int   g_cnt[NN];                  // zeroed at start (static init + scan re-zeroes)
__device__ int   g_rowptr[NN + 1];
__device__ int   g_cur[NN];
__device__ int   g_csrc[EE];
__device__ float g_w[EE];

// ---------------- CSR build ----------------
__global__ void k_hist(const int* __restrict__ dst, int E) {
    int e = blockIdx.x * 256 + threadIdx.x;
    if (e < E) atomicAdd(&g_cnt[dst[e]], 1);
}
__global__ __launch_bounds__(1024) void k_scan(int n, int E) {
    __shared__ int sums[1024];
    int t = threadIdx.x;
    int chunk = (n + 1023) >> 10;
    int s0 = t * chunk, s1 = min(s0 + chunk, n);
    int local = 0;
    for (int i = s0; i < s1; i++) local += g_cnt[i];
    sums[t] = local;
    __syncthreads();
    #pragma unroll
    for (int off = 1; off < 1024; off <<= 1) {
        int x = (t >= off) ? sums[t - off] : 0;
        __syncthreads();
        sums[t] += x;
        __syncthreads();
    }
    int run = sums[t] - local;
    for (int i = s0; i < s1; i++) {
        int c = g_cnt[i];
        g_cnt[i] = 0;            // re-zero for the NEXT graph replay
        g_rowptr[i] = run;
        g_cur[i] = run;
        run += c;
    }
    if (t == 0) g_rowptr[n] = E;
}
__global__ void k_scatter(const int* __restrict__ src, const int* __restrict__ dst, int E) {
    int e = blockIdx.x * 256 + threadIdx.x;
    if (e >= E) return;
    int pos = atomicAdd(&g_cur[dst[e]], 1);
    g_csrc[pos] = src[e];
}

// ================= tensor-core GEMM: C[M,N] = A[M,K] @ B[K,N] =================
// fp32 in/out, internally bf16 hi/lo split (3 mma products) for ~1e-5 accuracy.
// 64x128 CTA tile (acc = 32 regs) -> ~100 regs, 2 CTAs/SM WITHOUT spills:
// one CTA's mma phase hides the other's load/split/sync phase.

__device__ __forceinline__ void ldm_x4(uint32_t* r, uint32_t addr) {
    asm volatile("ldmatrix.sync.aligned.m8n8.x4.shared.b16 {%0,%1,%2,%3}, [%4];"
        : "=r"(r[0]), "=r"(r[1]), "=r"(r[2]), "=r"(r[3]) : "r"(addr));
}
__device__ __forceinline__ void ldm_x2t(uint32_t* r, uint32_t addr) {
    asm volatile("ldmatrix.sync.aligned.m8n8.x2.trans.shared.b16 {%0,%1}, [%2];"
        : "=r"(r[0]), "=r"(r[1]) : "r"(addr));
}
__device__ __forceinline__ void mma16816(float* c, const uint32_t* a, const uint32_t* b) {
    asm volatile("mma.sync.aligned.m16n8k16.row.col.f32.bf16.bf16.f32 "
        "{%0,%1,%2,%3}, {%4,%5,%6,%7}, {%8,%9}, {%0,%1,%2,%3};"
        : "+f"(c[0]), "+f"(c[1]), "+f"(c[2]), "+f"(c[3])
        : "r"(a[0]), "r"(a[1]), "r"(a[2]), "r"(a[3]), "r"(b[0]), "r"(b[1]));
}
__device__ __forceinline__ void split2(float x, __nv_bfloat16& h, __nv_bfloat16& l) {
    h = __float2bfloat16(x);
    l = __float2bfloat16(x - __bfloat162float(h));
}

#define APAD 8
#define BPAD 8

__global__ __launch_bounds__(256, 2) void k_mma_split(
    const float* __restrict__ A, const float* __restrict__ B,
    float* __restrict__ C, int M, int N, int K)
{
    __shared__ __nv_bfloat16 As[2][64][32 + APAD];    // hi/lo planes, 64x32
    __shared__ __nv_bfloat16 Bs[2][32][128 + BPAD];   // hi/lo planes, 32x128

    const int tid  = threadIdx.x;
    const int lane = tid & 31;
    const int wid  = tid >> 5;
    const int wm   = (wid & 1) * 32;    // 2 warps along M (32 rows each)
    const int wn   = (wid >> 1) * 32;   // 4 warps along N (32 cols each)
    const int bm   = blockIdx.y * 64;
    const int bn   = blockIdx.x * 128;

    float acc[2][4][4] = {};

    for (int k0 = 0; k0 < K; k0 += 32) {
        // A tile: 64x32 fp32 = 512 float4 -> 2 per thread
        #pragma unroll
        for (int i = 0; i < 2; i++) {
            int idx = tid + i * 256;
            int r  = idx >> 3;
            int c4 = (idx & 7) * 4;
            float4 v = make_float4(0.f, 0.f, 0.f, 0.f);
            if (bm + r < M) v = *(const float4*)(A + (size_t)(bm + r) * K + k0 + c4);
            union { __nv_bfloat16 b[4]; uint2 u; } ph, pl;
            split2(v.x, ph.b[0], pl.b[0]); split2(v.y, ph.b[1], pl.b[1]);
            split2(v.z, ph.b[2], pl.b[2]); split2(v.w, ph.b[3], pl.b[3]);
            *(uint2*)&As[0][r][c4] = ph.u;
            *(uint2*)&As[1][r][c4] = pl.u;
        }
        // B tile: 32x128 fp32 = 1024 float4 -> 4 per thread
        #pragma unroll
        for (int i = 0; i < 4; i++) {
            int idx = tid + i * 256;
            int r  = idx >> 5;
            int c4 = (idx & 31) * 4;
            float4 v = *(const float4*)(B + (size_t)(k0 + r) * N + bn + c4);
            union { __nv_bfloat16 b[4]; uint2 u; } ph, pl;
            split2(v.x, ph.b[0], pl.b[0]); split2(v.y, ph.b[1], pl.b[1]);
            split2(v.z, ph.b[2], pl.b[2]); split2(v.w, ph.b[3], pl.b[3]);
            *(uint2*)&Bs[0][r][c4] = ph.u;
            *(uint2*)&Bs[1][r][c4] = pl.u;
        }
        __syncthreads();

        #pragma unroll
        for (int ks = 0; ks < 2; ks++) {
            uint32_t bh[4][2], bl[4][2];
            #pragma unroll
            for (int nf = 0; nf < 4; nf++) {
                int rr = ks * 16 + (lane & 15);
                int cc = wn + nf * 8;
                ldm_x2t(bh[nf], (uint32_t)__cvta_generic_to_shared(&Bs[0][rr][cc]));
                ldm_x2t(bl[nf], (uint32_t)__cvta_generic_to_shared(&Bs[1][rr][cc]));
            }
            #pragma unroll
            for (int mf = 0; mf < 2; mf++) {
                uint32_t ah[4], al[4];
                int rr = wm + mf * 16 + (lane & 15);
                int cc = ks * 16 + (lane >> 4) * 8;
                ldm_x4(ah, (uint32_t)__cvta_generic_to_shared(&As[0][rr][cc]));
                ldm_x4(al, (uint32_t)__cvta_generic_to_shared(&As[1][rr][cc]));
                #pragma unroll
                for (int nf = 0; nf < 4; nf++) {
                    mma16816(acc[mf][nf], ah, bh[nf]);
                    mma16816(acc[mf][nf], ah, bl[nf]);
                    mma16816(acc[mf][nf], al, bh[nf]);
                }
            }
        }
        __syncthreads();
    }

    #pragma unroll
    for (int mf = 0; mf < 2; mf++) {
        int r0 = bm + wm + mf * 16 + (lane >> 2);
        #pragma unroll
        for (int nf = 0; nf < 4; nf++) {
            int c = bn + wn + nf * 8 + (lane & 3) * 2;
            if (r0 < M) {
                C[(size_t)r0 * N + c]     = acc[mf][nf][0];
                C[(size_t)r0 * N + c + 1] = acc[mf][nf][1];
            }
            if (r0 + 8 < M) {
                C[(size_t)(r0 + 8) * N + c]     = acc[mf][nf][2];
                C[(size_t)(r0 + 8) * N + c + 1] = acc[mf][nf][3];
            }
        }
    }
}

// ======= fused per-node: scores + online softmax + agg + ELU + (@W2) =======
// W2 staged in swizzled shared memory (stride 31, conflict-free epilogue LDS).
__global__ __launch_bounds__(256) void k_attn(const float* __restrict__ att,
                                              const float* __restrict__ W2,
                                              float* __restrict__ h2, int n)
{
    extern __shared__ float W2s[];   // [512 rows][stride 31]
    int tid = threadIdx.y * 32 + threadIdx.x;
    for (int idx = tid; idx < HID * DOUT; idx += 256) {
        int k = idx / DOUT, j = idx % DOUT;
        int row = (k & 3) * 128 + (k >> 2);
        W2s[row * 31 + j] = W2[idx];
    }
    __syncthreads();

    int d = blockIdx.x * 8 + threadIdx.y;
    int lane = threadIdx.x;
    if (d < n) {
        int beg = g_rowptr[d], end = g_rowptr[d + 1];

        const float4* hdp = (const float4*)(g_h + (size_t)d * HID);
        const float4* ap  = (const float4*)att;
        float4 hd[4], av[4];
        #pragma unroll
        for (int i = 0; i < 4; i++) {
            hd[i] = hdp[i * 32 + lane];
            av[i] = __ldg(&ap[i * 32 + lane]);
        }

        float m = -CUDART_INF_F, den = 0.f;
        float4 acc[4];
        #pragma unroll
        for (int i = 0; i < 4; i++) acc[i] = make_float4(0.f, 0.f, 0.f, 0.f);

        float4 nb[4];
        if (beg < end) {
            const float4* p0 = (const float4*)(g_h + (size_t)g_csrc[beg] * HID);
            #pragma unroll
            for (int i = 0; i < 4; i++) nb[i] = p0[i * 32 + lane];
        }

        for (int j = beg; j < end; j++) {
            float4 hs[4];
            #pragma unroll
            for (int i = 0; i < 4; i++) hs[i] = nb[i];

            if (j + 1 < end) {
                const float4* pn = (const float4*)(g_h + (size_t)g_csrc[j + 1] * HID);
                #pragma unroll
                for (int i = 0; i < 4; i++) nb[i] = pn[i * 32 + lane];
            }

            float p = 0.f;
            #pragma unroll
            for (int i = 0; i < 4; i++) {
                float4 a = hd[i];
                float4 b = hs[i];
                float v;
                v = a.x + b.x; v = v > 0.f ? v : 0.2f * v; p = fmaf(v, av[i].x, p);
                v = a.y + b.y; v = v > 0.f ? v : 0.2f * v; p = fmaf(v, av[i].y, p);
                v = a.z + b.z; v = v > 0.f ? v : 0.2f * v; p = fmaf(v, av[i].z, p);
                v = a.w + b.w; v = v > 0.f ? v : 0.2f * v; p = fmaf(v, av[i].w, p);
            }
            #pragma unroll
            for (int o = 16; o; o >>= 1) p += __shfl_xor_sync(0xffffffffu, p, o);

            if (lane == 0) g_w[j] = p;

            if (p > m) {
                float scale = expf(m - p);
                den *= scale;
                #pragma unroll
                for (int i = 0; i < 4; i++) {
                    acc[i].x *= scale; acc[i].y *= scale;
                    acc[i].z *= scale; acc[i].w *= scale;
                }
                m = p;
            }
            float w = expf(p - m);
            den += w;
            #pragma unroll
            for (int i = 0; i < 4; i++) {
                acc[i].x = fmaf(w, hs[i].x, acc[i].x);
                acc[i].y = fmaf(w, hs[i].y, acc[i].y);
                acc[i].z = fmaf(w, hs[i].z, acc[i].z);
                acc[i].w = fmaf(w, hs[i].w, acc[i].w);
            }
        }

        float h2acc[DOUT];
        #pragma unroll
        for (int j = 0; j < DOUT; j++) h2acc[j] = 0.f;

        if (end > beg) {
            float inv = 1.f / den;
            #pragma unroll
            for (int i = 0; i < 4; i++) {
                float hv[4];
                hv[0] = acc[i].x * inv; hv[0] = hv[0] > 0.f ? hv[0] : expm1f(hv[0]);
                hv[1] = acc[i].y * inv; hv[1] = hv[1] > 0.f ? hv[1] : expm1f(hv[1]);
                hv[2] = acc[i].z * inv; hv[2] = hv[2] > 0.f ? hv[2] : expm1f(hv[2]);
                hv[3] = acc[i].w * inv; hv[3] = hv[3] > 0.f ? hv[3] : expm1f(hv[3]);
                #pragma unroll
                for (int c = 0; c < 4; c++) {
                    const float* w2r = W2s + (size_t)(c * 128 + i * 32 + lane) * 31;
                    float x = hv[c];
                    #pragma unroll
                    for (int j = 0; j < DOUT; j++)
                        h2acc[j] = fmaf(x, w2r[j], h2acc[j]);
                }
            }
            for (int j = beg + lane; j < end; j += 32)
                g_w[j] = expf(g_w[j] - m) * inv;
        }

        #pragma unroll
        for (int j = 0; j < DOUT; j++)
            #pragma unroll
            for (int o = 16; o; o >>= 1)
                h2acc[j] += __shfl_xor_sync(0xffffffffu, h2acc[j], o);
        #pragma unroll
        for (int j = 0; j < DOUT; j++)
            if (lane == j) h2[(size_t)d * DOUT + j] = h2acc[j];
    }
}

// ======= 30-dim aggregation: a30[d] = sum_e w_e * h2[src_e] =======
__global__ __launch_bounds__(256) void k_agg30(const float* __restrict__ h2, int n)
{
    int d = blockIdx.x * 8 + threadIdx.y;
    if (d >= n) return;
    int lane = threadIdx.x;
    int beg = g_rowptr[d], end = g_rowptr[d + 1];

    float a = 0.f;
    float nv = 0.f, nw = 0.f;
    if (beg < end) {
        nw = g_w[beg];
        if (lane < DOUT) nv = h2[(size_t)g_csrc[beg] * DOUT + lane];
    }
    for (int j = beg; j < end; j++) {
        float v = nv, w = nw;
        if (j + 1 < end) {
            nw = g_w[j + 1];
            if (lane < DOUT) nv = h2[(size_t)g_csrc[j + 1] * DOUT + lane];
        }
        a = fmaf(w, v, a);
    }
    if (lane < DOUT) g_a30[(size_t)d * DOUT + lane] = a;
}

// ======= expand: h3 = elu(a30 @ W2^T), warp-per-node, W2 in smem =======
__global__ __launch_bounds__(256) void k_expand(const float* __restrict__ W2, int n)
{
    extern __shared__ float W2s[];   // [512][31]
    int tid = threadIdx.y * 32 + threadIdx.x;
    for (int idx = tid; idx < HID * DOUT; idx += 256) {
        int r = idx / DOUT, j = idx % DOUT;
        W2s[r * 31 + j] = W2[idx];
    }
    __syncthreads();

    int d = blockIdx.x * 8 + threadIdx.y;
    if (d >= n) return;
    int lane = threadIdx.x;

    float a[DOUT];
    const float* ar = g_a30 + (size_t)d * DOUT;
    #pragma unroll
    for (int j = 0; j < DOUT; j++) a[j] = __ldg(&ar[j]);

    float* op = g_h3 + (size_t)d * HID;
    #pragma unroll
    for (int mblk = 0; mblk < HID / 32; mblk++) {
        int c = mblk * 32 + lane;
        const float* w2r = W2s + (size_t)c * 31;
        float s = 0.f;
        #pragma unroll
        for (int j = 0; j < DOUT; j++) s = fmaf(a[j], w2r[j], s);
        op[c] = s > 0.f ? s : expm1f(s);
    }
}

// ---------------- launch ----------------
extern "C" void kernel_launch(void* const* d_in, const int* in_sizes, int n_in,
                              void* d_out, int out_size)
{
    const float* features = (const float*)d_in[0];
    const int*   eidx     = (const int*)d_in[1];
    const float* W1       = (const float*)d_in[2];
    const float* att1     = (const float*)d_in[3];
    const float* W2       = (const float*)d_in[4];
    const float* W4       = (const float*)d_in[5];
    float* out = (float*)d_out;

    const int n = in_sizes[0] / DIN;      // 50000
    const int E = in_sizes[1] / 2;        // 300000
    const int* src = eidx;
    const int* dst = eidx + E;

    float* h;   cudaGetSymbolAddress((void**)&h,   g_h);
    float* h3;  cudaGetSymbolAddress((void**)&h3,  g_h3);

    cudaFuncSetAttribute(k_attn,   cudaFuncAttributeMaxDynamicSharedMemorySize, W2S_BYTES);
    cudaFuncSetAttribute(k_expand, cudaFuncAttributeMaxDynamicSharedMemorySize, W2S_BYTES);

    const dim3 warp8(32, 8);

    // launches 0-2: CSR build
    k_hist<<<(E + 255) / 256, 256>>>(dst, E);
    k_scan<<<1, 1024>>>(n, E);
    k_scatter<<<(E + 255) / 256, 256>>>(src, dst, E);

    // launch 3 (ncu profiles THIS): h = X @ W1  (64x128 tile, 2 CTAs/SM)
    {
        dim3 g(HID / 128, (n + 63) / 64);
        k_mma_split<<<g, 256>>>(features, W1, h, n, HID, DIN);
    }

    // fused GATv2 + h2 projection (smem W2)
    k_attn<<<(n + 7) / 8, warp8, W2S_BYTES>>>(att1, W2, out, n);

    // 30-dim tied-alpha aggregation of h2
    k_agg30<<<(n + 7) / 8, warp8>>>(out, n);

    // h3 = elu(a30 @ W2^T)
    k_expand<<<(n + 7) / 8, warp8, W2S_BYTES>>>(W2, n);

    // h4 = h3 @ W4
    {
        dim3 g(DIN / 128, (n + 63) / 64);
        k_mma_split<<<g, 256>>>(h3, W4, out + (size_t)n * DOUT, n, DIN, HID);
    }
}